// round 16
// baseline (speedup 1.0000x reference)
#include <cuda_runtime.h>
#include <math.h>

// ---------------- constants ----------------
#define MAXW     24
#define NGT      40
#define EPSF     1e-7f
#define FULLMASK 0xffffffffu
#define NBL      192           // 64 batches * 3 levels
#define MAXENT   400
#define KMAX     5
#define LDEPTH   5
#define NFB      11            // focal chunks per batch: 8 (lvl0) + 2 (lvl1) + 1 (lvl2)
#define NFOCAL   (64 * NFB)    // 704
#define GTPB     4             // GTs per stage block
#define NGRP     (NGT / GTPB)  // 10 groups per (b,level)
#define NST1     (NBL * NGRP)  // 1920 stage blocks
#define NBLK1    (NST1 + NFOCAL)
#define TA       256           // kernel-2 block size

struct __align__(16) Stage {
    int   n_pos;
    int   cells[10];
    float biou, cxg, cyg, twt, tht, fx, fy;
    int   pad[2];              // -> 80 bytes, int4-copyable
};

__device__ Stage g_stage[NBL * NGT];
__device__ float g_fpart[NFOCAL];
__device__ float g_part[NBL * 4];
__device__ int   g_cnt2 = 0;        // self-resetting

__device__ __forceinline__ float sigf(float x)  { return 1.0f / (1.0f + expf(-x)); }

__device__ __forceinline__ float fast_splus(float x) {
    return fmaxf(x, 0.0f) + __logf(1.0f + __expf(-fabsf(x)));
}

__device__ __forceinline__ float focal0(float x) {
    float t   = __expf(-fabsf(x));
    float inv = __fdividef(1.0f, 1.0f + t);
    float prob = (x >= 0.0f) ? inv : t * inv;
    float ce0  = fmaxf(x, 0.0f) + __logf(1.0f + t);
    return 0.75f * prob * prob * ce0;
}

__device__ __forceinline__ float iou_vals(float p1, float p2, float p3, float p4,
                                          float gxx, float gyy, float s,
                                          float tx1, float ty1, float tx2, float ty2, float tA)
{
    float pcx = (sigf(p1) + gxx) * s;
    float pcy = (sigf(p2) + gyy) * s;
    float pw  = expf(fminf(fmaxf(p3, -5.0f), 5.0f)) * s;
    float ph  = expf(fminf(fmaxf(p4, -5.0f), 5.0f)) * s;
    float px1 = pcx - pw * 0.5f, py1 = pcy - ph * 0.5f;
    float px2 = pcx + pw * 0.5f, py2 = pcy + ph * 0.5f;
    float iw = fmaxf(fminf(px2, tx2) - fmaxf(px1, tx1), 0.0f);
    float ih = fmaxf(fminf(py2, ty2) - fmaxf(py1, ty1), 0.0f);
    float inter = iw * ih;
    float aa = (px2 - px1) * (py2 - py1);
    return inter / (aa + tA - inter + EPSF);
}

__device__ __forceinline__ float pred_iou(const float* __restrict__ pred, int HW, int cell,
                                          float gxx, float gyy, float s,
                                          float tx1, float ty1, float tx2, float ty2, float tA)
{
    return iou_vals(pred[HW + cell], pred[2 * HW + cell], pred[3 * HW + cell], pred[4 * HW + cell],
                    gxx, gyy, s, tx1, ty1, tx2, ty2, tA);
}

// ---------------- Kernel 1: stage blocks (4 GTs each) + focal blocks ----------------
__global__ void __launch_bounds__(128)
stage_kernel(const float* __restrict__ p0,
             const float* __restrict__ p1,
             const float* __restrict__ p2,
             const float* __restrict__ tgt)
{
    const int tid  = threadIdx.x;
    const int lane = tid & 31;
    const int wid  = tid >> 5;

    // ================= focal blocks =================
    if (blockIdx.x >= NST1) {
        __shared__ float fsm[4];
        const int fid = blockIdx.x - NST1;
        const int fb  = fid / NFB;
        const int j   = fid - fb * NFB;
        const float* base;
        int off, cnt;
        if (j < 8)       { base = p0 + (long long)fb * 7 * 25600; off = j * 3200;       cnt = 3200; }
        else if (j < 10) { base = p1 + (long long)fb * 7 * 6400;  off = (j - 8) * 3200; cnt = 3200; }
        else             { base = p2 + (long long)fb * 7 * 1600;  off = 0;              cnt = 1600; }

        const float4* v4 = (const float4*)(base + off);
        float sum = 0.0f;
        for (int i = tid; i < cnt / 4; i += 128) {
            float4 xv = v4[i];
            sum += focal0(xv.x) + focal0(xv.y) + focal0(xv.z) + focal0(xv.w);
        }
        for (int o = 16; o; o >>= 1) sum += __shfl_xor_sync(FULLMASK, sum, o);
        if (lane == 0) fsm[wid] = sum;
        __syncthreads();
        if (tid == 0) g_fpart[fid] = fsm[0] + fsm[1] + fsm[2] + fsm[3];
        return;
    }

    // ================= stage blocks: 4 GTs serially =================
    __shared__ float mcC[4][10];
    __shared__ int   mcS[4][10];
    __shared__ float rls[4];
    __shared__ int   rlc[4];

    const int bl    = blockIdx.x / NGRP;
    const int grp   = blockIdx.x - bl * NGRP;
    const int g0    = grp * GTPB;
    const int b     = bl / 3;
    const int level = bl % 3;

    const float* predB = (level == 0) ? p0 : (level == 1) ? p1 : p2;
    const int W  = (level == 0) ? 160 : (level == 1) ? 80 : 40;
    const int HW = W * W;
    const float s = (level == 0) ? 0.00625f : (level == 1) ? 0.0125f : 0.025f;
    const float* pred = predB + (long long)b * 7 * HW;

    const float INF = __int_as_float(0x7f800000);

    for (int j = 0; j < GTPB; j++) {
        const int g = g0 + j;
        Stage& st = g_stage[bl * NGT + g];

        const float* t = &tgt[b * NGT * 7 + g * 7];
        float cls = t[0], cx = t[1], cy = t[2], w = t[3], h = t[4], fx = t[5], fy = t[6];
        float size = fmaxf(w, h) * 1280.0f;
        bool valid = (cls == 0.0f) &&
                     ((level == 0) ? (size < 128.0f)
                      : (level == 1) ? (size >= 48.0f && size < 288.0f)
                                     : (size >= 128.0f));
        if (!valid) {                     // block-uniform
            if (tid == 0) st.n_pos = 0;
            continue;
        }

        float cxg = cx / s, cyg = cy / s;
        float x1b = (cx - w * 0.5f) / s, x2b = (cx + w * 0.5f) / s;
        float y1b = (cy - h * 0.5f) / s, y2b = (cy + h * 0.5f) / s;
        float tx1 = cx - w * 0.5f, ty1 = cy - h * 0.5f;
        float tx2 = cx + w * 0.5f, ty2 = cy + h * 0.5f;
        float tA  = (tx2 - tx1) * (ty2 - ty1);

        int gx0 = max(0, (int)floorf(fminf(cxg - 2.5f, x1b)));
        int gx1 = min(W - 1, (int)ceilf(fmaxf(cxg + 2.5f, x2b)));
        int gy0 = max(0, (int)floorf(fminf(cyg - 2.5f, y1b)));
        int gy1 = min(W - 1, (int)ceilf(fmaxf(cyg + 2.5f, y2b)));
        int wx = gx1 - gx0 + 1, wy = gy1 - gy0 + 1;
        if (wx > MAXW) wx = MAXW;
        if (wy > MAXW) wy = MAXW;
        int nwin = (wx > 0 && wy > 0) ? wx * wy : 0;
        float rwx = 1.0f / (float)wx;

        // pass 1: issue all window loads
        float v0[KMAX], v1[KMAX], v2[KMAX], v3[KMAX], v4c[KMAX];
        float gX[KMAX], gY[KMAX];
        bool  act[KMAX];
        #pragma unroll
        for (int k = 0; k < KMAX; k++) {
            int si = tid + k * 128;
            act[k] = false;
            if (si < nwin) {
                int iy = (int)(((float)si + 0.5f) * rwx);
                int ix = si - iy * wx;
                float gxx = (float)(gx0 + ix), gyy = (float)(gy0 + iy);
                bool ic = (fabsf(gxx - cxg) < 2.5f) && (fabsf(gyy - cyg) < 2.5f);
                bool ib = (gxx >= x1b) && (gxx < x2b) && (gyy >= y1b) && (gyy < y2b);
                if (ic || ib) {
                    act[k] = true;
                    gX[k] = gxx; gY[k] = gyy;
                    int cell = (gy0 + iy) * W + (gx0 + ix);
                    v0[k] = pred[cell];
                    v1[k] = pred[HW + cell];
                    v2[k] = pred[2 * HW + cell];
                    v3[k] = pred[3 * HW + cell];
                    v4c[k] = pred[4 * HW + cell];
                }
            }
        }

        // pass 2: cost + per-lane top-LDEPTH
        float lc[LDEPTH];
        int   ls[LDEPTH];
        #pragma unroll
        for (int i = 0; i < LDEPTH; i++) { lc[i] = INF; ls[i] = 0x7fffffff; }

        float lis = 0.0f;
        int   lnc = 0;
        #pragma unroll
        for (int k = 0; k < KMAX; k++) {
            if (!act[k]) continue;
            int si = tid + k * 128;
            float iou = iou_vals(v1[k], v2[k], v3[k], v4c[k], gX[k], gY[k], s, tx1, ty1, tx2, ty2, tA);
            float c = fast_splus(-v0[k]) - 3.0f * __logf(iou + EPSF);
            lis += iou;
            lnc += 1;
            if (c < lc[LDEPTH - 1]) {
                lc[LDEPTH - 1] = c; ls[LDEPTH - 1] = si;
                #pragma unroll
                for (int i = LDEPTH - 1; i > 0; i--) {
                    if (lc[i] < lc[i - 1]) {
                        float tc = lc[i]; lc[i] = lc[i - 1]; lc[i - 1] = tc;
                        int   ts = ls[i]; ls[i] = ls[i - 1]; ls[i - 1] = ts;
                    }
                }
            }
        }

        for (int off = 16; off; off >>= 1) {
            lis += __shfl_xor_sync(FULLMASK, lis, off);
            lnc += __shfl_xor_sync(FULLMASK, lnc, off);
        }
        if (lane == 0) { rls[wid] = lis; rlc[wid] = lnc; }
        if (tid < 40) { mcC[tid / 10][tid % 10] = INF; mcS[tid / 10][tid % 10] = 0x7fffffff; }
        __syncthreads();
        lis = rls[0] + rls[1] + rls[2] + rls[3];
        lnc = rlc[0] + rlc[1] + rlc[2] + rlc[3];

        if (lnc == 0) {
            // fallback (practically unreachable): nearest cell, warp 0 only
            if (wid == 0) {
                float bd = INF; int bc = 0x7fffffff;
                for (int cell = lane; cell < HW; cell += 32) {
                    float gxx = (float)(cell % W), gyy = (float)(cell / W);
                    float d = (gxx - cxg) * (gxx - cxg) + (gyy - cyg) * (gyy - cyg);
                    if (d < bd) { bd = d; bc = cell; }
                }
                for (int off = 16; off; off >>= 1) {
                    float od = __shfl_xor_sync(FULLMASK, bd, off);
                    int   oc = __shfl_xor_sync(FULLMASK, bc, off);
                    if (od < bd || (od == bd && oc < bc)) { bd = od; bc = oc; }
                }
                if (lane == 0) {
                    float gxx = (float)(bc % W), gyy = (float)(bc / W);
                    st.cells[0] = bc;
                    st.n_pos = 1;
                    st.biou  = pred_iou(pred, HW, bc, gxx, gyy, s, tx1, ty1, tx2, ty2, tA);
                    st.cxg = cxg; st.cyg = cyg;
                    st.twt = logf(w / s + EPSF);
                    st.tht = logf(h / s + EPSF);
                    st.fx = fx; st.fy = fy;
                }
            }
            __syncthreads();
            continue;
        }

        const int n_pos = min(min(10, lnc), max(1, (int)floorf(lis)));

        for (int k = 0; k < n_pos; k++) {
            float hc = lc[0]; int hs = ls[0];
            for (int off = 16; off; off >>= 1) {
                float oc = __shfl_xor_sync(FULLMASK, hc, off);
                int   os = __shfl_xor_sync(FULLMASK, hs, off);
                if (oc < hc || (oc == hc && os < hs)) { hc = oc; hs = os; }
            }
            if (lane == 0) { mcC[wid][k] = hc; mcS[wid][k] = hs; }
            if (lc[0] == hc && ls[0] == hs) {
                #pragma unroll
                for (int i = 0; i < LDEPTH - 1; i++) { lc[i] = lc[i + 1]; ls[i] = ls[i + 1]; }
                lc[LDEPTH - 1] = INF; ls[LDEPTH - 1] = 0x7fffffff;
            }
        }
        __syncthreads();

        if (wid == 0) {
            int j1 = lane;
            int j2 = lane + 32;
            float k1 = mcC[j1 / 10][j1 % 10];
            int   s1 = mcS[j1 / 10][j1 % 10];
            float k2 = (lane < 8) ? mcC[j2 / 10][j2 % 10] : INF;
            int   s2v = (lane < 8) ? mcS[j2 / 10][j2 % 10] : 0x7fffffff;

            int cell0 = 0;
            for (int k = 0; k < n_pos; k++) {
                float mc2; int ms2; bool firstIsMin;
                if (k1 < k2 || (k1 == k2 && s1 < s2v)) { mc2 = k1; ms2 = s1; firstIsMin = true; }
                else                                    { mc2 = k2; ms2 = s2v; firstIsMin = false; }
                float hc = mc2; int hs = ms2;
                for (int off = 16; off; off >>= 1) {
                    float oc = __shfl_xor_sync(FULLMASK, hc, off);
                    int   os = __shfl_xor_sync(FULLMASK, hs, off);
                    if (oc < hc || (oc == hc && os < hs)) { hc = oc; hs = os; }
                }
                int iy = hs / wx, ix = hs - iy * wx;
                int cell = (gy0 + iy) * W + (gx0 + ix);
                if (k == 0) cell0 = cell;
                if (lane == 0) st.cells[k] = cell;
                if (firstIsMin) { if (k1 == hc && s1 == hs) { k1 = INF; s1 = 0x7fffffff; } }
                else            { if (k2 == hc && s2v == hs) { k2 = INF; s2v = 0x7fffffff; } }
            }
            if (lane == 0) {
                float gxx = (float)(cell0 % W), gyy = (float)(cell0 / W);
                st.n_pos = n_pos;
                st.biou  = pred_iou(pred, HW, cell0, gxx, gyy, s, tx1, ty1, tx2, ty2, tA);
                st.cxg = cxg; st.cyg = cyg;
                st.twt = logf(w / s + EPSF);
                st.tht = logf(h / s + EPSF);
                st.fx = fx; st.fy = fy;
            }
        }
        __syncthreads();   // protect shared reuse across GT iterations
    }
}

// final combine: fixed order over g_part + g_fpart -> out[0]. Deterministic.
__device__ void final_combine(float* __restrict__ out, int tid, float* red)
{
    float v = 0.0f;
    for (int i = tid; i < NBL; i += TA) {
        int b = i / 3, l = i % 3;
        float HWf = (l == 0) ? 25600.0f : (l == 1) ? 6400.0f : 1600.0f;
        int nf = (l == 0) ? 8 : (l == 1) ? 2 : 1;
        int f0 = (l == 0) ? 0 : (l == 1) ? 8 : 10;
        float objt = g_part[i * 4 + 0];
        for (int jj = 0; jj < nf; jj++) objt += g_fpart[b * NFB + f0 + jj];
        float bxs  = g_part[i * 4 + 1];
        float fts  = g_part[i * 4 + 2];
        float npos = fmaxf(g_part[i * 4 + 3], 1.0f);
        v += objt / HWf + 5.0f * bxs / npos + fts / npos;
    }
    red[tid] = v; __syncthreads();
    for (int off = TA / 2; off; off >>= 1) { if (tid < off) red[tid] += red[tid + off]; __syncthreads(); }
    if (tid == 0) out[0] = red[0] / 64.0f;
}

// ---------------- Kernel 2: apply blocks + fused final ----------------
__global__ void __launch_bounds__(TA)
apply_kernel(const float* __restrict__ p0,
             const float* __restrict__ p1,
             const float* __restrict__ p2,
             float* __restrict__ out)
{
    __shared__ float red[TA];
    __shared__ int   sFinal;
    __shared__ __align__(16) Stage sSt[NGT];
    __shared__ int   entCell[MAXENT];
    __shared__ int   entG[MAXENT];
    __shared__ int   sOff[NGT];
    __shared__ int   sM;
    __shared__ float wr[8][4];

    const int tid  = threadIdx.x;
    const int lane = tid & 31;
    const int wid  = tid >> 5;

    const int bl    = blockIdx.x;
    const int b     = bl / 3;
    const int level = bl % 3;
    const float* pred = (level == 0) ? p0 : (level == 1) ? p1 : p2;
    const int W  = (level == 0) ? 160 : (level == 1) ? 80 : 40;
    const int HW = W * W;
    const float s = (level == 0) ? 0.00625f : (level == 1) ? 0.0125f : 0.025f;
    pred += (long long)b * 7 * HW;

    // cooperative vectorized load of this bl's 40 Stage structs (200 int4)
    {
        const int4* src = (const int4*)(g_stage + bl * NGT);
        int4* dst = (int4*)sSt;
        for (int i = tid; i < (NGT * (int)sizeof(Stage)) / 16; i += TA) dst[i] = src[i];
    }
    __syncthreads();

    if (tid < NGT) {
        int off = 0;
        #pragma unroll
        for (int g2 = 0; g2 < NGT; g2++) { if (g2 < tid) off += sSt[g2].n_pos; }
        sOff[tid] = off;
        if (tid == NGT - 1) sM = off + sSt[tid].n_pos;
    }
    __syncthreads();
    if (tid < NGT) {
        int off = sOff[tid];
        int np  = sSt[tid].n_pos;
        for (int k = 0; k < np; k++) { entCell[off + k] = sSt[tid].cells[k]; entG[off + k] = tid; }
    }
    __syncthreads();
    const int M = sM;

    float corr = 0.0f, boxs = 0.0f, foots = 0.0f;
    int   nown = 0;

    for (int e = tid; e < M; e += TA) {
        int c  = entCell[e];
        int ge = entG[e];
        float z = sSt[ge].biou;
        bool owner = true;
        for (int e2 = 0; e2 < M; e2++) {
            if (entCell[e2] == c && e2 != e) {
                int g2 = entG[e2];
                z = fmaxf(z, sSt[g2].biou);
                if (g2 > ge) owner = false;
            }
        }
        if (!owner) continue;
        nown++;

        float gxx = (float)(c % W), gyy = (float)(c / W);

        float x = pred[c];
        float prob = sigf(x);
        float l1e  = log1pf(expf(-fabsf(x)));
        float ce   = fmaxf(x, 0.0f) - x * z + l1e;
        float ce0  = fmaxf(x, 0.0f) + l1e;
        float pt   = prob * z + (1.0f - prob) * (1.0f - z);
        float at   = 0.25f * z + 0.75f * (1.0f - z);
        float om   = 1.0f - pt;
        corr += at * om * om * ce - 0.75f * prob * prob * ce0;

        float p1v = pred[HW + c], p2v = pred[2 * HW + c];
        float p3v = pred[3 * HW + c], p4v = pred[4 * HW + c];
        float pcx = (sigf(p1v) + gxx) * s;
        float pcy = (sigf(p2v) + gyy) * s;
        float pw  = expf(fminf(fmaxf(p3v, -5.0f), 5.0f)) * s;
        float ph  = expf(fminf(fmaxf(p4v, -5.0f), 5.0f)) * s;
        float tcx = sSt[ge].cxg * s;
        float tcy = sSt[ge].cyg * s;
        float tw  = expf(sSt[ge].twt) * s;
        float th  = expf(sSt[ge].tht) * s;
        float px1 = pcx - pw * 0.5f, py1 = pcy - ph * 0.5f;
        float px2 = pcx + pw * 0.5f, py2 = pcy + ph * 0.5f;
        float qx1 = tcx - tw * 0.5f, qy1 = tcy - th * 0.5f;
        float qx2 = tcx + tw * 0.5f, qy2 = tcy + th * 0.5f;
        float iw = fmaxf(fminf(px2, qx2) - fmaxf(px1, qx1), 0.0f);
        float ih = fmaxf(fminf(py2, qy2) - fmaxf(py1, qy1), 0.0f);
        float inter = iw * ih;
        float uni = pw * ph + tw * th - inter + EPSF;
        float iou = inter / uni;
        float rho2 = (pcx - tcx) * (pcx - tcx) + (pcy - tcy) * (pcy - tcy);
        float cw  = fmaxf(px2, qx2) - fminf(px1, qx1);
        float chh = fmaxf(py2, qy2) - fminf(py1, qy1);
        float c2  = cw * cw + chh * chh + EPSF;
        float dat = atanf(tw / (th + EPSF)) - atanf(pw / (ph + EPSF));
        float v = 0.4052847345693511f * dat * dat;
        float alpha = v / (1.0f - iou + v + EPSF);
        float ciou = iou - rho2 / c2 - alpha * v;
        boxs += 1.0f - ciou;

        float p5v = pred[5 * HW + c], p6v = pred[6 * HW + c];
        float d1 = fabsf(sigf(p5v) - sSt[ge].fx);
        float d2 = fabsf(sigf(p6v) - sSt[ge].fy);
        float s1 = (d1 < 1.0f) ? 0.5f * d1 * d1 : d1 - 0.5f;
        float s2 = (d2 < 1.0f) ? 0.5f * d2 * d2 : d2 - 0.5f;
        foots += s1 + s2;
    }

    // single-pass deterministic reduction
    float fnown = (float)nown;
    for (int off = 16; off; off >>= 1) {
        corr  += __shfl_xor_sync(FULLMASK, corr,  off);
        boxs  += __shfl_xor_sync(FULLMASK, boxs,  off);
        foots += __shfl_xor_sync(FULLMASK, foots, off);
        fnown += __shfl_xor_sync(FULLMASK, fnown, off);
    }
    if (lane == 0) { wr[wid][0] = corr; wr[wid][1] = boxs; wr[wid][2] = foots; wr[wid][3] = fnown; }
    __syncthreads();
    if (tid == 0) {
        float a0 = 0, a1 = 0, a2 = 0, a3 = 0;
        #pragma unroll
        for (int k = 0; k < 8; k++) { a0 += wr[k][0]; a1 += wr[k][1]; a2 += wr[k][2]; a3 += wr[k][3]; }
        g_part[bl * 4 + 0] = a0;
        g_part[bl * 4 + 1] = a1;
        g_part[bl * 4 + 2] = a2;
        g_part[bl * 4 + 3] = a3;
    }
    __syncthreads();

    __threadfence();
    if (tid == 0) {
        int old = atomicAdd(&g_cnt2, 1);
        sFinal = (old == NBL - 1);
        if (sFinal) g_cnt2 = 0;
    }
    __syncthreads();
    if (sFinal) { __threadfence(); final_combine(out, tid, red); }
}

// ---------------- launch ----------------
extern "C" void kernel_launch(void* const* d_in, const int* in_sizes, int n_in,
                              void* d_out, int out_size)
{
    const float* p0  = (const float*)d_in[0];
    const float* p1  = (const float*)d_in[1];
    const float* p2  = (const float*)d_in[2];
    const float* tgt = (const float*)d_in[3];

    stage_kernel<<<NBLK1, 128>>>(p0, p1, p2, tgt);
    apply_kernel<<<NBL, TA>>>(p0, p1, p2, (float*)d_out);
}

// round 17
// speedup vs baseline: 1.2797x; 1.2797x over previous
#include <cuda_runtime.h>
#include <math.h>

// ---------------- constants ----------------
#define MAXW     24
#define NGT      40
#define EPSF     1e-7f
#define FULLMASK 0xffffffffu
#define NBL      192           // 64 batches * 3 levels
#define MAXENT   400
#define KMAX     5
#define LDEPTH   5
#define NFB      11            // focal chunks per batch: 8 (lvl0) + 2 (lvl1) + 1 (lvl2)
#define NFOCAL   (64 * NFB)    // 704
#define NSTAGE   (NBL * NGT)   // 7680
#define TOTAL2   (NBL + NFOCAL) // 896 blocks in kernel 2
#define TA       256           // kernel-2 block size

struct __align__(16) Stage {
    int   n_pos;
    int   cells[10];
    float biou, cxg, cyg, twt, tht, fx, fy;
    int   pad[2];              // -> 80 bytes, int4-copyable
};

__device__ Stage g_stage[NSTAGE];
__device__ float g_fpart[NFOCAL];
__device__ float g_part[NBL * 4];
__device__ int   g_cnt2 = 0;        // self-resetting

__device__ __forceinline__ float sigf(float x)  { return 1.0f / (1.0f + expf(-x)); }

// fast sigmoid (MUFU-based)
__device__ __forceinline__ float fsig(float x) {
    float t   = __expf(-fabsf(x));
    float inv = __fdividef(1.0f, 1.0f + t);
    return (x >= 0.0f) ? inv : t * inv;
}

__device__ __forceinline__ float fast_splus(float x) {
    return fmaxf(x, 0.0f) + __logf(1.0f + __expf(-fabsf(x)));
}

__device__ __forceinline__ float focal0(float x) {
    float t   = __expf(-fabsf(x));
    float inv = __fdividef(1.0f, 1.0f + t);
    float prob = (x >= 0.0f) ? inv : t * inv;
    float ce0  = fmaxf(x, 0.0f) + __logf(1.0f + t);
    return 0.75f * prob * prob * ce0;
}

// IoU from already-loaded channel values — FAST intrinsics (feeds iou_sum/z/cost;
// continuous use + measure-zero decision boundaries -> 1e-6 error acceptable)
__device__ __forceinline__ float iou_vals(float p1, float p2, float p3, float p4,
                                          float gxx, float gyy, float s,
                                          float tx1, float ty1, float tx2, float ty2, float tA)
{
    float pcx = (fsig(p1) + gxx) * s;
    float pcy = (fsig(p2) + gyy) * s;
    float pw  = __expf(fminf(fmaxf(p3, -5.0f), 5.0f)) * s;
    float ph  = __expf(fminf(fmaxf(p4, -5.0f), 5.0f)) * s;
    float px1 = pcx - pw * 0.5f, py1 = pcy - ph * 0.5f;
    float px2 = pcx + pw * 0.5f, py2 = pcy + ph * 0.5f;
    float iw = fmaxf(fminf(px2, tx2) - fmaxf(px1, tx1), 0.0f);
    float ih = fmaxf(fminf(py2, ty2) - fmaxf(py1, ty1), 0.0f);
    float inter = iw * ih;
    float aa = (px2 - px1) * (py2 - py1);
    return __fdividef(inter, aa + tA - inter + EPSF);
}

__device__ __forceinline__ float pred_iou(const float* __restrict__ pred, int HW, int cell,
                                          float gxx, float gyy, float s,
                                          float tx1, float ty1, float tx2, float ty2, float tA)
{
    return iou_vals(pred[HW + cell], pred[2 * HW + cell], pred[3 * HW + cell], pred[4 * HW + cell],
                    gxx, gyy, s, tx1, ty1, tx2, ty2, tA);
}

// ---------------- Kernel 1: stage blocks only ----------------
__global__ void __launch_bounds__(128)
stage_kernel(const float* __restrict__ p0,
             const float* __restrict__ p1,
             const float* __restrict__ p2,
             const float* __restrict__ tgt)
{
    __shared__ float mcC[4][10];
    __shared__ int   mcS[4][10];
    __shared__ float rls[4];
    __shared__ int   rlc[4];
    __shared__ float sIou[MAXW * MAXW];   // per-slot IoU (valid only where candidate active)

    const int tid  = threadIdx.x;
    const int lane = tid & 31;
    const int wid  = tid >> 5;

    const int gw    = blockIdx.x;
    const int bl    = gw / NGT;
    const int g     = gw - bl * NGT;
    const int b     = bl / 3;
    const int level = bl % 3;

    Stage& st = g_stage[gw];

    const float* t = &tgt[b * NGT * 7 + g * 7];
    float cls = t[0], cx = t[1], cy = t[2], w = t[3], h = t[4], fx = t[5], fy = t[6];
    float size = fmaxf(w, h) * 1280.0f;
    bool valid = (cls == 0.0f) &&
                 ((level == 0) ? (size < 128.0f)
                  : (level == 1) ? (size >= 48.0f && size < 288.0f)
                                 : (size >= 128.0f));
    if (!valid) {
        if (tid == 0) st.n_pos = 0;
        return;
    }

    const float* predB = (level == 0) ? p0 : (level == 1) ? p1 : p2;
    const int W  = (level == 0) ? 160 : (level == 1) ? 80 : 40;
    const int HW = W * W;
    const float s = (level == 0) ? 0.00625f : (level == 1) ? 0.0125f : 0.025f;
    const float* pred = predB + (long long)b * 7 * HW;

    const float INF = __int_as_float(0x7f800000);

    float cxg = cx / s, cyg = cy / s;
    float x1b = (cx - w * 0.5f) / s, x2b = (cx + w * 0.5f) / s;
    float y1b = (cy - h * 0.5f) / s, y2b = (cy + h * 0.5f) / s;
    float tx1 = cx - w * 0.5f, ty1 = cy - h * 0.5f;
    float tx2 = cx + w * 0.5f, ty2 = cy + h * 0.5f;
    float tA  = (tx2 - tx1) * (ty2 - ty1);

    int gx0 = max(0, (int)floorf(fminf(cxg - 2.5f, x1b)));
    int gx1 = min(W - 1, (int)ceilf(fmaxf(cxg + 2.5f, x2b)));
    int gy0 = max(0, (int)floorf(fminf(cyg - 2.5f, y1b)));
    int gy1 = min(W - 1, (int)ceilf(fmaxf(cyg + 2.5f, y2b)));
    int wx = gx1 - gx0 + 1, wy = gy1 - gy0 + 1;
    if (wx > MAXW) wx = MAXW;
    if (wy > MAXW) wy = MAXW;
    int nwin = (wx > 0 && wy > 0) ? wx * wy : 0;
    float rwx = 1.0f / (float)wx;

    // pass 1: issue all window loads
    float v0[KMAX], v1[KMAX], v2[KMAX], v3[KMAX], v4c[KMAX];
    float gX[KMAX], gY[KMAX];
    bool  act[KMAX];
    #pragma unroll
    for (int k = 0; k < KMAX; k++) {
        int si = tid + k * 128;
        act[k] = false;
        if (si < nwin) {
            int iy = (int)(((float)si + 0.5f) * rwx);
            int ix = si - iy * wx;
            float gxx = (float)(gx0 + ix), gyy = (float)(gy0 + iy);
            bool ic = (fabsf(gxx - cxg) < 2.5f) && (fabsf(gyy - cyg) < 2.5f);
            bool ib = (gxx >= x1b) && (gxx < x2b) && (gyy >= y1b) && (gyy < y2b);
            if (ic || ib) {
                act[k] = true;
                gX[k] = gxx; gY[k] = gyy;
                int cell = (gy0 + iy) * W + (gx0 + ix);
                v0[k] = pred[cell];
                v1[k] = pred[HW + cell];
                v2[k] = pred[2 * HW + cell];
                v3[k] = pred[3 * HW + cell];
                v4c[k] = pred[4 * HW + cell];
            }
        }
    }

    // pass 2: cost + per-lane top-LDEPTH; stash IoU per slot in smem
    float lc[LDEPTH];
    int   ls[LDEPTH];
    #pragma unroll
    for (int i = 0; i < LDEPTH; i++) { lc[i] = INF; ls[i] = 0x7fffffff; }

    float lis = 0.0f;
    int   lnc = 0;
    #pragma unroll
    for (int k = 0; k < KMAX; k++) {
        if (!act[k]) continue;
        int si = tid + k * 128;
        float iou = iou_vals(v1[k], v2[k], v3[k], v4c[k], gX[k], gY[k], s, tx1, ty1, tx2, ty2, tA);
        float c = fast_splus(-v0[k]) - 3.0f * __logf(iou + EPSF);
        sIou[si] = iou;
        lis += iou;
        lnc += 1;
        if (c < lc[LDEPTH - 1]) {
            lc[LDEPTH - 1] = c; ls[LDEPTH - 1] = si;
            #pragma unroll
            for (int i = LDEPTH - 1; i > 0; i--) {
                if (lc[i] < lc[i - 1]) {
                    float tc = lc[i]; lc[i] = lc[i - 1]; lc[i - 1] = tc;
                    int   ts = ls[i]; ls[i] = ls[i - 1]; ls[i - 1] = ts;
                }
            }
        }
    }

    for (int off = 16; off; off >>= 1) {
        lis += __shfl_xor_sync(FULLMASK, lis, off);
        lnc += __shfl_xor_sync(FULLMASK, lnc, off);
    }
    if (lane == 0) { rls[wid] = lis; rlc[wid] = lnc; }
    if (tid < 40) { mcC[tid / 10][tid % 10] = INF; mcS[tid / 10][tid % 10] = 0x7fffffff; }
    __syncthreads();
    lis = rls[0] + rls[1] + rls[2] + rls[3];
    lnc = rlc[0] + rlc[1] + rlc[2] + rlc[3];

    if (lnc == 0) {
        // fallback (practically unreachable): nearest cell, warp 0 only
        if (wid == 0) {
            float bd = INF; int bc = 0x7fffffff;
            for (int cell = lane; cell < HW; cell += 32) {
                float gxx = (float)(cell % W), gyy = (float)(cell / W);
                float d = (gxx - cxg) * (gxx - cxg) + (gyy - cyg) * (gyy - cyg);
                if (d < bd) { bd = d; bc = cell; }
            }
            for (int off = 16; off; off >>= 1) {
                float od = __shfl_xor_sync(FULLMASK, bd, off);
                int   oc = __shfl_xor_sync(FULLMASK, bc, off);
                if (od < bd || (od == bd && oc < bc)) { bd = od; bc = oc; }
            }
            if (lane == 0) {
                float gxx = (float)(bc % W), gyy = (float)(bc / W);
                st.cells[0] = bc;
                st.n_pos = 1;
                st.biou  = pred_iou(pred, HW, bc, gxx, gyy, s, tx1, ty1, tx2, ty2, tA);
                st.cxg = cxg; st.cyg = cyg;
                st.twt = logf(w / s + EPSF);
                st.tht = logf(h / s + EPSF);
                st.fx = fx; st.fy = fy;
            }
        }
        return;
    }

    const int n_pos = min(min(10, lnc), max(1, (int)floorf(lis)));

    for (int k = 0; k < n_pos; k++) {
        float hc = lc[0]; int hs = ls[0];
        for (int off = 16; off; off >>= 1) {
            float oc = __shfl_xor_sync(FULLMASK, hc, off);
            int   os = __shfl_xor_sync(FULLMASK, hs, off);
            if (oc < hc || (oc == hc && os < hs)) { hc = oc; hs = os; }
        }
        if (lane == 0) { mcC[wid][k] = hc; mcS[wid][k] = hs; }
        if (lc[0] == hc && ls[0] == hs) {
            #pragma unroll
            for (int i = 0; i < LDEPTH - 1; i++) { lc[i] = lc[i + 1]; ls[i] = ls[i + 1]; }
            lc[LDEPTH - 1] = INF; ls[LDEPTH - 1] = 0x7fffffff;
        }
    }
    __syncthreads();

    if (wid == 0) {
        int j1 = lane;
        int j2 = lane + 32;
        float k1 = mcC[j1 / 10][j1 % 10];
        int   s1 = mcS[j1 / 10][j1 % 10];
        float k2 = (lane < 8) ? mcC[j2 / 10][j2 % 10] : INF;
        int   s2v = (lane < 8) ? mcS[j2 / 10][j2 % 10] : 0x7fffffff;

        int slot0 = 0;
        for (int k = 0; k < n_pos; k++) {
            float mc2; int ms2; bool firstIsMin;
            if (k1 < k2 || (k1 == k2 && s1 < s2v)) { mc2 = k1; ms2 = s1; firstIsMin = true; }
            else                                    { mc2 = k2; ms2 = s2v; firstIsMin = false; }
            float hc = mc2; int hs = ms2;
            for (int off = 16; off; off >>= 1) {
                float oc = __shfl_xor_sync(FULLMASK, hc, off);
                int   os = __shfl_xor_sync(FULLMASK, hs, off);
                if (oc < hc || (oc == hc && os < hs)) { hc = oc; hs = os; }
            }
            int iy = hs / wx, ix = hs - iy * wx;
            int cell = (gy0 + iy) * W + (gx0 + ix);
            if (k == 0) slot0 = hs;
            if (lane == 0) st.cells[k] = cell;
            if (firstIsMin) { if (k1 == hc && s1 == hs) { k1 = INF; s1 = 0x7fffffff; } }
            else            { if (k2 == hc && s2v == hs) { k2 = INF; s2v = 0x7fffffff; } }
        }
        if (lane == 0) {
            st.n_pos = n_pos;
            st.biou  = sIou[slot0];            // pass-2 value, no reload
            st.cxg = cxg; st.cyg = cyg;
            st.twt = logf(w / s + EPSF);
            st.tht = logf(h / s + EPSF);
            st.fx = fx; st.fy = fy;
        }
    }
}

// final combine: fixed order over g_part + g_fpart -> out[0]. Deterministic.
__device__ void final_combine(float* __restrict__ out, int tid, float* red)
{
    float v = 0.0f;
    for (int i = tid; i < NBL; i += TA) {
        int b = i / 3, l = i % 3;
        float HWf = (l == 0) ? 25600.0f : (l == 1) ? 6400.0f : 1600.0f;
        int nf = (l == 0) ? 8 : (l == 1) ? 2 : 1;
        int f0 = (l == 0) ? 0 : (l == 1) ? 8 : 10;
        float objt = g_part[i * 4 + 0];
        for (int j = 0; j < nf; j++) objt += g_fpart[b * NFB + f0 + j];
        float bxs  = g_part[i * 4 + 1];
        float fts  = g_part[i * 4 + 2];
        float npos = fmaxf(g_part[i * 4 + 3], 1.0f);
        v += objt / HWf + 5.0f * bxs / npos + fts / npos;
    }
    red[tid] = v; __syncthreads();
    for (int off = TA / 2; off; off >>= 1) { if (tid < off) red[tid] += red[tid + off]; __syncthreads(); }
    if (tid == 0) out[0] = red[0] / 64.0f;
}

// ---------------- Kernel 2: apply blocks + focal blocks + fused final ----------------
__global__ void __launch_bounds__(TA)
apply_kernel(const float* __restrict__ p0,
             const float* __restrict__ p1,
             const float* __restrict__ p2,
             float* __restrict__ out)
{
    __shared__ float red[TA];
    __shared__ int   sFinal;

    const int tid  = threadIdx.x;
    const int lane = tid & 31;
    const int wid  = tid >> 5;

    // ================= focal blocks =================
    if (blockIdx.x >= NBL) {
        __shared__ float fsm[8];
        const int fid = blockIdx.x - NBL;
        const int fb  = fid / NFB;
        const int j   = fid - fb * NFB;
        const float* base;
        int off, cnt;
        if (j < 8)       { base = p0 + (long long)fb * 7 * 25600; off = j * 3200;       cnt = 3200; }
        else if (j < 10) { base = p1 + (long long)fb * 7 * 6400;  off = (j - 8) * 3200; cnt = 3200; }
        else             { base = p2 + (long long)fb * 7 * 1600;  off = 0;              cnt = 1600; }

        const float4* v4 = (const float4*)(base + off);
        float sum = 0.0f;
        for (int i = tid; i < cnt / 4; i += TA) {
            float4 xv = v4[i];
            sum += focal0(xv.x) + focal0(xv.y) + focal0(xv.z) + focal0(xv.w);
        }
        for (int o = 16; o; o >>= 1) sum += __shfl_xor_sync(FULLMASK, sum, o);
        if (lane == 0) fsm[wid] = sum;
        __syncthreads();
        if (tid == 0) {
            float s8 = 0.0f;
            #pragma unroll
            for (int k = 0; k < 8; k++) s8 += fsm[k];
            g_fpart[fid] = s8;
        }

        __threadfence();
        if (tid == 0) {
            int old = atomicAdd(&g_cnt2, 1);
            sFinal = (old == TOTAL2 - 1);
            if (sFinal) g_cnt2 = 0;
        }
        __syncthreads();
        if (sFinal) { __threadfence(); final_combine(out, tid, red); }
        return;
    }

    // ================= apply blocks =================
    __shared__ __align__(16) Stage sSt[NGT];
    __shared__ int   entCell[MAXENT];
    __shared__ int   entG[MAXENT];
    __shared__ int   sOff[NGT];
    __shared__ int   sM;
    __shared__ float wr[8][4];

    const int bl    = blockIdx.x;
    const int b     = bl / 3;
    const int level = bl % 3;
    const float* pred = (level == 0) ? p0 : (level == 1) ? p1 : p2;
    const int W  = (level == 0) ? 160 : (level == 1) ? 80 : 40;
    const int HW = W * W;
    const float s = (level == 0) ? 0.00625f : (level == 1) ? 0.0125f : 0.025f;
    pred += (long long)b * 7 * HW;

    {
        const int4* src = (const int4*)(g_stage + bl * NGT);
        int4* dst = (int4*)sSt;
        for (int i = tid; i < (NGT * (int)sizeof(Stage)) / 16; i += TA) dst[i] = src[i];
    }
    __syncthreads();

    if (tid < NGT) {
        int off = 0;
        #pragma unroll
        for (int g2 = 0; g2 < NGT; g2++) { if (g2 < tid) off += sSt[g2].n_pos; }
        sOff[tid] = off;
        if (tid == NGT - 1) sM = off + sSt[tid].n_pos;
    }
    __syncthreads();
    if (tid < NGT) {
        int off = sOff[tid];
        int np  = sSt[tid].n_pos;
        for (int k = 0; k < np; k++) { entCell[off + k] = sSt[tid].cells[k]; entG[off + k] = tid; }
    }
    __syncthreads();
    const int M = sM;

    float corr = 0.0f, boxs = 0.0f, foots = 0.0f;
    int   nown = 0;

    for (int e = tid; e < M; e += TA) {
        int c  = entCell[e];
        int ge = entG[e];
        float z = sSt[ge].biou;
        bool owner = true;
        for (int e2 = 0; e2 < M; e2++) {
            if (entCell[e2] == c && e2 != e) {
                int g2 = entG[e2];
                z = fmaxf(z, sSt[g2].biou);
                if (g2 > ge) owner = false;
            }
        }
        if (!owner) continue;
        nown++;

        float gxx = (float)(c % W), gyy = (float)(c / W);

        float x = pred[c];
        float prob = sigf(x);
        float l1e  = log1pf(expf(-fabsf(x)));
        float ce   = fmaxf(x, 0.0f) - x * z + l1e;
        float ce0  = fmaxf(x, 0.0f) + l1e;
        float pt   = prob * z + (1.0f - prob) * (1.0f - z);
        float at   = 0.25f * z + 0.75f * (1.0f - z);
        float om   = 1.0f - pt;
        corr += at * om * om * ce - 0.75f * prob * prob * ce0;

        float p1v = pred[HW + c], p2v = pred[2 * HW + c];
        float p3v = pred[3 * HW + c], p4v = pred[4 * HW + c];
        float pcx = (sigf(p1v) + gxx) * s;
        float pcy = (sigf(p2v) + gyy) * s;
        float pw  = expf(fminf(fmaxf(p3v, -5.0f), 5.0f)) * s;
        float ph  = expf(fminf(fmaxf(p4v, -5.0f), 5.0f)) * s;
        float tcx = sSt[ge].cxg * s;
        float tcy = sSt[ge].cyg * s;
        float tw  = expf(sSt[ge].twt) * s;
        float th  = expf(sSt[ge].tht) * s;
        float px1 = pcx - pw * 0.5f, py1 = pcy - ph * 0.5f;
        float px2 = pcx + pw * 0.5f, py2 = pcy + ph * 0.5f;
        float qx1 = tcx - tw * 0.5f, qy1 = tcy - th * 0.5f;
        float qx2 = tcx + tw * 0.5f, qy2 = tcy + th * 0.5f;
        float iw = fmaxf(fminf(px2, qx2) - fmaxf(px1, qx1), 0.0f);
        float ih = fmaxf(fminf(py2, qy2) - fmaxf(py1, qy1), 0.0f);
        float inter = iw * ih;
        float uni = pw * ph + tw * th - inter + EPSF;
        float iou = inter / uni;
        float rho2 = (pcx - tcx) * (pcx - tcx) + (pcy - tcy) * (pcy - tcy);
        float cw  = fmaxf(px2, qx2) - fminf(px1, qx1);
        float chh = fmaxf(py2, qy2) - fminf(py1, qy1);
        float c2  = cw * cw + chh * chh + EPSF;
        float dat = atanf(tw / (th + EPSF)) - atanf(pw / (ph + EPSF));
        float v = 0.4052847345693511f * dat * dat;
        float alpha = v / (1.0f - iou + v + EPSF);
        float ciou = iou - rho2 / c2 - alpha * v;
        boxs += 1.0f - ciou;

        float p5v = pred[5 * HW + c], p6v = pred[6 * HW + c];
        float d1 = fabsf(sigf(p5v) - sSt[ge].fx);
        float d2 = fabsf(sigf(p6v) - sSt[ge].fy);
        float s1 = (d1 < 1.0f) ? 0.5f * d1 * d1 : d1 - 0.5f;
        float s2 = (d2 < 1.0f) ? 0.5f * d2 * d2 : d2 - 0.5f;
        foots += s1 + s2;
    }

    float fnown = (float)nown;
    for (int off = 16; off; off >>= 1) {
        corr  += __shfl_xor_sync(FULLMASK, corr,  off);
        boxs  += __shfl_xor_sync(FULLMASK, boxs,  off);
        foots += __shfl_xor_sync(FULLMASK, foots, off);
        fnown += __shfl_xor_sync(FULLMASK, fnown, off);
    }
    if (lane == 0) { wr[wid][0] = corr; wr[wid][1] = boxs; wr[wid][2] = foots; wr[wid][3] = fnown; }
    __syncthreads();
    if (tid == 0) {
        float a0 = 0, a1 = 0, a2 = 0, a3 = 0;
        #pragma unroll
        for (int k = 0; k < 8; k++) { a0 += wr[k][0]; a1 += wr[k][1]; a2 += wr[k][2]; a3 += wr[k][3]; }
        g_part[bl * 4 + 0] = a0;
        g_part[bl * 4 + 1] = a1;
        g_part[bl * 4 + 2] = a2;
        g_part[bl * 4 + 3] = a3;
    }
    __syncthreads();

    __threadfence();
    if (tid == 0) {
        int old = atomicAdd(&g_cnt2, 1);
        sFinal = (old == TOTAL2 - 1);
        if (sFinal) g_cnt2 = 0;
    }
    __syncthreads();
    if (sFinal) { __threadfence(); final_combine(out, tid, red); }
}

// ---------------- launch ----------------
extern "C" void kernel_launch(void* const* d_in, const int* in_sizes, int n_in,
                              void* d_out, int out_size)
{
    const float* p0  = (const float*)d_in[0];
    const float* p1  = (const float*)d_in[1];
    const float* p2  = (const float*)d_in[2];
    const float* tgt = (const float*)d_in[3];

    stage_kernel<<<NSTAGE, 128>>>(p0, p1, p2, tgt);
    apply_kernel<<<TOTAL2, TA>>>(p0, p1, p2, (float*)d_out);
}